// round 9
// baseline (speedup 1.0000x reference)
#include <cuda_runtime.h>
#include <cuda_bf16.h>
#include <cstdint>

#define Bb 4
#define Tt 2048
#define Cc 1024
#define NHh 16
#define Dd 64
#define Mtot (Bb * Tt)   // 8192

// ------------------------- scratch (__device__ globals) --------------------
__device__ float g_qkv[(size_t)Bb * Tt * 3 * Cc];    // [B,T,3C] fp32
__device__ __nv_bfloat16 g_xh[(size_t)Mtot * Cc];
__device__ uint8_t       g_x8h[(size_t)Mtot * Cc];
__device__ uint8_t       g_x8l[(size_t)Mtot * Cc];
__device__ __nv_bfloat16 g_wh[(size_t)3 * Cc * Cc];
__device__ uint8_t       g_w8h[(size_t)3 * Cc * Cc];
__device__ uint8_t       g_w8l[(size_t)3 * Cc * Cc];
__device__ __nv_bfloat16 g_ph[(size_t)Cc * Cc];
__device__ uint8_t       g_p8h[(size_t)Cc * Cc];
__device__ uint8_t       g_p8l[(size_t)Cc * Cc];
__device__ __nv_bfloat16 g_ah[(size_t)Mtot * Cc];
__device__ uint8_t       g_a8h[(size_t)Mtot * Cc];
__device__ uint8_t       g_a8l[(size_t)Mtot * Cc];
// head-major [b*16+h][t][d] bf16 for attention
__device__ __nv_bfloat16 g_qh[(size_t)Mtot * Cc];
__device__ __nv_bfloat16 g_ql[(size_t)Mtot * Cc];
__device__ __nv_bfloat16 g_kh[(size_t)Mtot * Cc];
__device__ __nv_bfloat16 g_kl[(size_t)Mtot * Cc];
__device__ __nv_bfloat16 g_vh[(size_t)Mtot * Cc];
__device__ __nv_bfloat16 g_vl[(size_t)Mtot * Cc];

// scales: A-type (x / attention-out): hi x 2^4, lo x 2^13
//         B-type (weights):           hi x 2^9, lo x 2^18
// corrections Ah8*Bl8 and Al8*Bh8 both carry combined scale 2^22.
#define SH_A 16.0f
#define SL_A 8192.0f
#define SH_B 512.0f
#define SL_B 262144.0f
#define INVCS (1.0f / 4194304.0f)

// ------------------------- helpers -----------------------------------------
__device__ __forceinline__ uint32_t smem_u32(const void* p) {
    uint32_t a;
    asm("{ .reg .u64 t; cvta.to.shared.u64 t, %1; cvt.u32.u64 %0, t; }"
        : "=r"(a) : "l"(p));
    return a;
}

__device__ __forceinline__ void ldmx4(uint32_t& r0, uint32_t& r1,
                                      uint32_t& r2, uint32_t& r3, uint32_t addr) {
    asm volatile("ldmatrix.sync.aligned.m8n8.x4.shared.b16 {%0,%1,%2,%3}, [%4];"
                 : "=r"(r0), "=r"(r1), "=r"(r2), "=r"(r3) : "r"(addr));
}

__device__ __forceinline__ void ldmx4t(uint32_t& r0, uint32_t& r1,
                                       uint32_t& r2, uint32_t& r3, uint32_t addr) {
    asm volatile("ldmatrix.sync.aligned.m8n8.x4.trans.shared.b16 {%0,%1,%2,%3}, [%4];"
                 : "=r"(r0), "=r"(r1), "=r"(r2), "=r"(r3) : "r"(addr));
}

__device__ __forceinline__ void mma16816(float* d, const uint32_t* a,
                                         uint32_t b0, uint32_t b1) {
    asm volatile(
        "mma.sync.aligned.m16n8k16.row.col.f32.bf16.bf16.f32 "
        "{%0,%1,%2,%3}, {%4,%5,%6,%7}, {%8,%9}, {%0,%1,%2,%3};"
        : "+f"(d[0]), "+f"(d[1]), "+f"(d[2]), "+f"(d[3])
        : "r"(a[0]), "r"(a[1]), "r"(a[2]), "r"(a[3]), "r"(b0), "r"(b1));
}

__device__ __forceinline__ void mma_fp8(float* d, const uint32_t* a,
                                        uint32_t b0, uint32_t b1) {
    asm volatile(
        "mma.sync.aligned.m16n8k32.row.col.f32.e4m3.e4m3.f32 "
        "{%0,%1,%2,%3}, {%4,%5,%6,%7}, {%8,%9}, {%0,%1,%2,%3};"
        : "+f"(d[0]), "+f"(d[1]), "+f"(d[2]), "+f"(d[3])
        : "r"(a[0]), "r"(a[1]), "r"(a[2]), "r"(a[3]), "r"(b0), "r"(b1));
}

__device__ __forceinline__ uint32_t packbf(float lo, float hi) {
    uint32_t r;
    asm("cvt.rn.bf16x2.f32 %0, %1, %2;" : "=r"(r) : "f"(hi), "f"(lo));
    return r;
}

// pack two floats into e4m3x2: low byte = lo, high byte = hi
__device__ __forceinline__ uint16_t pack_e4m3(float lo, float hi) {
    uint16_t r;
    asm("cvt.rn.satfinite.e4m3x2.f32 %0, %1, %2;" : "=h"(r) : "f"(hi), "f"(lo));
    return r;
}

__device__ __forceinline__ void cp16(uint32_t dst, const void* src) {
    asm volatile("cp.async.cg.shared.global [%0], [%1], 16;" :: "r"(dst), "l"(src));
}
#define CP_COMMIT() asm volatile("cp.async.commit_group;" ::: "memory")
#define CP_WAIT0()  asm volatile("cp.async.wait_group 0;" ::: "memory")
#define CP_WAIT1()  asm volatile("cp.async.wait_group 1;" ::: "memory")
#define CP_WAIT2()  asm volatile("cp.async.wait_group 2;" ::: "memory")

// ---------------------------------------------------------------------------
// Hybrid GEMM: D = Ah*Bh (bf16, f32 acc) + 2^-22 * (Ah8*Bl8 + Al8*Bh8) (fp8)
// CTA tile 128x128, BK=32, 8 warps (2m x 4n), warp tile 64x32, 3-stage cp.async.
// ---------------------------------------------------------------------------
#define SPADB 80u   // bf16 tile byte row stride (64B data + 16 pad)
#define SPAD8 48u   // fp8 tile byte row stride (32B data + 16 pad)
#define OFF_AH 0u
#define OFF_BH 10240u
#define OFF_A8H 20480u
#define OFF_A8L 26624u
#define OFF_B8H 32768u
#define OFF_B8L 38912u
#define STG 45056u
#define GEMM_SMEM (3u * STG)   // 135168

__global__ __launch_bounds__(256, 1)
void gemm_hybrid(const __nv_bfloat16* __restrict__ Ah,
                 const uint8_t* __restrict__ A8h,
                 const uint8_t* __restrict__ A8l,
                 const __nv_bfloat16* __restrict__ Bh,
                 const uint8_t* __restrict__ B8h,
                 const uint8_t* __restrict__ B8l,
                 const float* __restrict__ bias,
                 float* __restrict__ Cout, int N, int K)
{
    extern __shared__ char gsm[];
    const uint32_t sb = smem_u32(gsm);

    const int tid  = threadIdx.x;
    const int wid  = tid >> 5;
    const int lane = tid & 31;
    const int mw   = wid >> 2;      // 0..1
    const int nw   = wid & 3;       // 0..3
    const int m0   = blockIdx.y * 128;
    const int n0   = blockIdx.x * 128;

    const int kq  = K >> 3;   // bf16 row stride in uint4
    const int k16 = K >> 4;   // fp8 row stride in uint4
    const int nk  = K >> 5;

    // loader coords
    const int rb = tid >> 2, cb = tid & 3;   // bf16: 2 chunks per thread
    const int r8 = tid >> 1, c8 = tid & 1;   // fp8:  1 chunk per tile per thread

    auto load_stage = [&](int st, int kc) {
        const uint32_t base = sb + (uint32_t)st * STG;
        // Ah / Bh bf16 (128 rows x 64B each)
#pragma unroll
        for (int i = 0; i < 2; i++) {
            const int r = rb + i * 64;
            const uint32_t so = (uint32_t)(r * SPADB + cb * 16);
            cp16(base + OFF_AH + so, (const uint4*)Ah + (size_t)(m0 + r) * kq + kc * 4 + cb);
            cp16(base + OFF_BH + so, (const uint4*)Bh + (size_t)(n0 + r) * kq + kc * 4 + cb);
        }
        // fp8 tiles (128 rows x 32B each)
        {
            const uint32_t so = (uint32_t)(r8 * SPAD8 + c8 * 16);
            const size_t ga = (size_t)(m0 + r8) * k16 + kc * 2 + c8;
            const size_t gb = (size_t)(n0 + r8) * k16 + kc * 2 + c8;
            cp16(base + OFF_A8H + so, (const uint4*)A8h + ga);
            cp16(base + OFF_A8L + so, (const uint4*)A8l + ga);
            cp16(base + OFF_B8H + so, (const uint4*)B8h + gb);
            cp16(base + OFF_B8L + so, (const uint4*)B8l + gb);
        }
    };

    const int lrow = lane & 15;
    const int lcol = (lane >> 4) * 16;   // byte offset of k-half
    uint32_t aoffB[4], boffB[2], aoff8[4], boff8[2];
#pragma unroll
    for (int mt = 0; mt < 4; mt++) {
        const int row = mw * 64 + mt * 16 + lrow;
        aoffB[mt] = (uint32_t)(row * SPADB + lcol);
        aoff8[mt] = (uint32_t)(row * SPAD8 + lcol);
    }
#pragma unroll
    for (int bg = 0; bg < 2; bg++) {
        const int row = nw * 32 + bg * 16 + lrow;
        boffB[bg] = (uint32_t)(row * SPADB + lcol);
        boff8[bg] = (uint32_t)(row * SPAD8 + lcol);
    }

    float acc[4][4][4], accC[4][4][4];
#pragma unroll
    for (int i = 0; i < 4; i++)
#pragma unroll
        for (int j = 0; j < 4; j++)
#pragma unroll
            for (int e = 0; e < 4; e++) { acc[i][j][e] = 0.f; accC[i][j][e] = 0.f; }

    load_stage(0, 0);
    CP_COMMIT();
    load_stage(1, 1);
    CP_COMMIT();

    int st = 0;
    for (int kc = 0; kc < nk; kc++) {
        if (kc + 2 < nk) load_stage((st + 2) % 3, kc + 2);
        CP_COMMIT();
        CP_WAIT2();
        __syncthreads();

        const uint32_t base = sb + (uint32_t)st * STG;
        // ---- bf16 hi passes (2 x k16) ----
#pragma unroll
        for (int ks = 0; ks < 2; ks++) {
            const uint32_t kb = ks * 32;
            uint32_t ah[4][4];
#pragma unroll
            for (int mt = 0; mt < 4; mt++)
                ldmx4(ah[mt][0], ah[mt][1], ah[mt][2], ah[mt][3],
                      base + OFF_AH + aoffB[mt] + kb);
            uint32_t bh[2][4];
#pragma unroll
            for (int bg = 0; bg < 2; bg++)
                ldmx4(bh[bg][0], bh[bg][1], bh[bg][2], bh[bg][3],
                      base + OFF_BH + boffB[bg] + kb);
#pragma unroll
            for (int mt = 0; mt < 4; mt++)
#pragma unroll
                for (int bg = 0; bg < 2; bg++)
#pragma unroll
                    for (int sub = 0; sub < 2; sub++)
                        mma16816(acc[mt][bg * 2 + sub], ah[mt],
                                 bh[bg][sub], bh[bg][sub + 2]);
        }
        // ---- fp8 correction passes (1 x k32 each) ----
        {
            uint32_t a8h[4][4], a8l[4][4];
#pragma unroll
            for (int mt = 0; mt < 4; mt++) {
                ldmx4(a8h[mt][0], a8h[mt][1], a8h[mt][2], a8h[mt][3],
                      base + OFF_A8H + aoff8[mt]);
                ldmx4(a8l[mt][0], a8l[mt][1], a8l[mt][2], a8l[mt][3],
                      base + OFF_A8L + aoff8[mt]);
            }
            uint32_t b8h[2][4], b8l[2][4];
#pragma unroll
            for (int bg = 0; bg < 2; bg++) {
                ldmx4(b8h[bg][0], b8h[bg][1], b8h[bg][2], b8h[bg][3],
                      base + OFF_B8H + boff8[bg]);
                ldmx4(b8l[bg][0], b8l[bg][1], b8l[bg][2], b8l[bg][3],
                      base + OFF_B8L + boff8[bg]);
            }
#pragma unroll
            for (int mt = 0; mt < 4; mt++)
#pragma unroll
                for (int bg = 0; bg < 2; bg++)
#pragma unroll
                    for (int sub = 0; sub < 2; sub++) {
                        const int nt = bg * 2 + sub;
                        mma_fp8(accC[mt][nt], a8h[mt],
                                b8l[bg][sub], b8l[bg][sub + 2]);
                        mma_fp8(accC[mt][nt], a8l[mt],
                                b8h[bg][sub], b8h[bg][sub + 2]);
                    }
        }
        __syncthreads();
        st = (st + 1) % 3;
    }

    const int erow = lane >> 2;
    const int ecol = (lane & 3) * 2;
#pragma unroll
    for (int mt = 0; mt < 4; mt++) {
#pragma unroll
        for (int nt = 0; nt < 4; nt++) {
            const int row = m0 + mw * 64 + mt * 16 + erow;
            const int col = n0 + nw * 32 + nt * 8 + ecol;
            const float b0 = bias[col], b1 = bias[col + 1];
            float2 v;
            v.x = acc[mt][nt][0] + accC[mt][nt][0] * INVCS + b0;
            v.y = acc[mt][nt][1] + accC[mt][nt][1] * INVCS + b1;
            *(float2*)(Cout + (size_t)row * N + col) = v;
            v.x = acc[mt][nt][2] + accC[mt][nt][2] * INVCS + b0;
            v.y = acc[mt][nt][3] + accC[mt][nt][3] * INVCS + b1;
            *(float2*)(Cout + (size_t)(row + 8) * N + col) = v;
        }
    }
}

// ---------------------------------------------------------------------------
// fp32 -> bf16 hi + fp8 hi/lo (scaled) split
// ---------------------------------------------------------------------------
__global__ void split_fp8(const float4* __restrict__ src,
                          __nv_bfloat162* __restrict__ hi,
                          uint16_t* __restrict__ h8,
                          uint16_t* __restrict__ l8,
                          int n4, float sH, float sL)
{
    int i = blockIdx.x * 256 + threadIdx.x;
    if (i >= n4) return;
    float4 v = src[i];
    __nv_bfloat16 hx = __float2bfloat16(v.x);
    __nv_bfloat16 hy = __float2bfloat16(v.y);
    __nv_bfloat16 hz = __float2bfloat16(v.z);
    __nv_bfloat16 hw = __float2bfloat16(v.w);
    __nv_bfloat162 a;
    a.x = hx; a.y = hy; hi[2 * i] = a;
    a.x = hz; a.y = hw; hi[2 * i + 1] = a;
    h8[2 * i]     = pack_e4m3(v.x * sH, v.y * sH);
    h8[2 * i + 1] = pack_e4m3(v.z * sH, v.w * sH);
    float lx = (v.x - __bfloat162float(hx)) * sL;
    float ly = (v.y - __bfloat162float(hy)) * sL;
    float lz = (v.z - __bfloat162float(hz)) * sL;
    float lw = (v.w - __bfloat162float(hw)) * sL;
    l8[2 * i]     = pack_e4m3(lx, ly);
    l8[2 * i + 1] = pack_e4m3(lz, lw);
}

// ---------------------------------------------------------------------------
// Fused RoPE + head-major relayout + hi/lo bf16 split of q,k,v (for flash).
// ---------------------------------------------------------------------------
__device__ __forceinline__ void split_store4(__nv_bfloat16* ph, __nv_bfloat16* pl,
                                             float a, float b, float c, float d)
{
    __nv_bfloat16 h0 = __float2bfloat16(a), h1 = __float2bfloat16(b);
    __nv_bfloat16 h2 = __float2bfloat16(c), h3 = __float2bfloat16(d);
    __nv_bfloat162 v;
    v.x = h0; v.y = h1; *(__nv_bfloat162*)ph = v;
    v.x = h2; v.y = h3; *(__nv_bfloat162*)(ph + 2) = v;
    v.x = __float2bfloat16(a - __bfloat162float(h0));
    v.y = __float2bfloat16(b - __bfloat162float(h1));
    *(__nv_bfloat162*)pl = v;
    v.x = __float2bfloat16(c - __bfloat162float(h2));
    v.y = __float2bfloat16(d - __bfloat162float(h3));
    *(__nv_bfloat162*)(pl + 2) = v;
}

__global__ void rope_split(const float* __restrict__ cosp,
                           const float* __restrict__ sinp)
{
    int idx = blockIdx.x * 256 + threadIdx.x;
    int ds = idx & 7;
    int h  = (idx >> 3) & 15;
    int t  = (idx >> 7) & 2047;
    int b  = idx >> 18;
    int d0 = ds * 4;

    const float* base = g_qkv + ((size_t)(b * Tt + t)) * (3 * Cc) + h * Dd;
    float4 q1 = *(const float4*)(base + d0);
    float4 q2 = *(const float4*)(base + d0 + 32);
    float4 k1 = *(const float4*)(base + Cc + d0);
    float4 k2 = *(const float4*)(base + Cc + d0 + 32);
    float4 v1 = *(const float4*)(base + 2 * Cc + d0);
    float4 v2 = *(const float4*)(base + 2 * Cc + d0 + 32);
    float4 cw = *(const float4*)(cosp + t * Dd + d0);
    float4 sw = *(const float4*)(sinp + t * Dd + d0);

    const float sc = 0.125f;
    float qa0 = (q1.x * cw.x - q2.x * sw.x) * sc;
    float qa1 = (q1.y * cw.y - q2.y * sw.y) * sc;
    float qa2 = (q1.z * cw.z - q2.z * sw.z) * sc;
    float qa3 = (q1.w * cw.w - q2.w * sw.w) * sc;
    float qb0 = (q2.x * cw.x + q1.x * sw.x) * sc;
    float qb1 = (q2.y * cw.y + q1.y * sw.y) * sc;
    float qb2 = (q2.z * cw.z + q1.z * sw.z) * sc;
    float qb3 = (q2.w * cw.w + q1.w * sw.w) * sc;
    float ka0 = k1.x * cw.x - k2.x * sw.x;
    float ka1 = k1.y * cw.y - k2.y * sw.y;
    float ka2 = k1.z * cw.z - k2.z * sw.z;
    float ka3 = k1.w * cw.w - k2.w * sw.w;
    float kb0 = k2.x * cw.x + k1.x * sw.x;
    float kb1 = k2.y * cw.y + k1.y * sw.y;
    float kb2 = k2.z * cw.z + k1.z * sw.z;
    float kb3 = k2.w * cw.w + k1.w * sw.w;

    size_t ob = (((size_t)(b * NHh + h)) * Tt + t) * Dd;
    split_store4(g_qh + ob + d0,      g_ql + ob + d0,      qa0, qa1, qa2, qa3);
    split_store4(g_qh + ob + d0 + 32, g_ql + ob + d0 + 32, qb0, qb1, qb2, qb3);
    split_store4(g_kh + ob + d0,      g_kl + ob + d0,      ka0, ka1, ka2, ka3);
    split_store4(g_kh + ob + d0 + 32, g_kl + ob + d0 + 32, kb0, kb1, kb2, kb3);
    split_store4(g_vh + ob + d0,      g_vl + ob + d0,      v1.x, v1.y, v1.z, v1.w);
    split_store4(g_vh + ob + d0 + 32, g_vl + ob + d0 + 32, v2.x, v2.y, v2.z, v2.w);
}

// ---------------------------------------------------------------------------
// Flash attention on mma.sync (bf16 hi/lo split, fp32 softmax).
// Epilogue writes bf16 hi -> g_ah and fp8 hi/lo -> g_a8h/g_a8l (proj inputs).
// ---------------------------------------------------------------------------
#define SROW 72
#define TILE_B 9216u

__global__ __launch_bounds__(128, 1) void flash_mma()
{
    extern __shared__ char fsm[];
    const uint32_t sb = smem_u32(fsm);

    const int bh = blockIdx.y;
    const int qt = (gridDim.x - 1) - blockIdx.x;
    const int q0 = qt * 64;
    const int tid = threadIdx.x, wid = tid >> 5, lane = tid & 31;

    const size_t hb = (size_t)bh * Tt * Dd;
    const __nv_bfloat16* Qh = g_qh + hb + (size_t)q0 * Dd;
    const __nv_bfloat16* Ql = g_ql + hb + (size_t)q0 * Dd;
    const __nv_bfloat16* Kh = g_kh + hb;
    const __nv_bfloat16* Kl = g_kl + hb;
    const __nv_bfloat16* Vh = g_vh + hb;
    const __nv_bfloat16* Vl = g_vl + hb;

    auto soff = [&](int buf, int mat) -> uint32_t {
        return sb + (uint32_t)(buf * 4 + mat) * TILE_B;
    };

    {
#pragma unroll
        for (int i = 0; i < 4; i++) {
            int lin = tid + i * 128;
            int r = lin >> 3, c = (lin & 7) * 8;
            uint32_t so = (uint32_t)(r * SROW + c) * 2;
            cp16(soff(1, 0) + so, Qh + (size_t)r * Dd + c);
            cp16(soff(1, 1) + so, Ql + (size_t)r * Dd + c);
        }
        CP_COMMIT();
#pragma unroll
        for (int i = 0; i < 4; i++) {
            int lin = tid + i * 128;
            int r = lin >> 3, c = (lin & 7) * 8;
            uint32_t so = (uint32_t)(r * SROW + c) * 2;
            cp16(soff(0, 0) + so, Kh + (size_t)r * Dd + c);
            cp16(soff(0, 1) + so, Kl + (size_t)r * Dd + c);
            cp16(soff(0, 2) + so, Vh + (size_t)r * Dd + c);
            cp16(soff(0, 3) + so, Vl + (size_t)r * Dd + c);
        }
        CP_COMMIT();
        CP_WAIT0();
        __syncthreads();
    }

    uint32_t QHf[4][4], QLf[4][4];
    {
        const int row = wid * 16 + (lane & 15);
        const int ck  = (lane >> 4) * 8;
#pragma unroll
        for (int kk = 0; kk < 4; kk++) {
            uint32_t ao = (uint32_t)(row * SROW + kk * 16 + ck) * 2;
            ldmx4(QHf[kk][0], QHf[kk][1], QHf[kk][2], QHf[kk][3], soff(1, 0) + ao);
            ldmx4(QLf[kk][0], QLf[kk][1], QLf[kk][2], QLf[kk][3], soff(1, 1) + ao);
        }
    }

    float O[8][4];
#pragma unroll
    for (int i = 0; i < 8; i++)
#pragma unroll
        for (int e = 0; e < 4; e++) O[i][e] = 0.f;
    float m0 = -1e30f, m1 = -1e30f, l0 = 0.f, l1 = 0.f;

    const int klrow = lane & 15;
    const int klk   = (lane >> 4) * 8;
    const int vg    = lane >> 3;
    const int vrow_in = (vg & 1) * 8 + (lane & 7);
    const int vcol_of = (vg >> 1) * 8;

    for (int jt = 0; jt <= qt; jt++) {
        const int buf = jt & 1;
        __syncthreads();
        if (jt < qt) {
            const int j1 = (jt + 1) * 64;
#pragma unroll
            for (int i = 0; i < 4; i++) {
                int lin = tid + i * 128;
                int r = lin >> 3, c = (lin & 7) * 8;
                uint32_t so = (uint32_t)(r * SROW + c) * 2;
                size_t gi = (size_t)(j1 + r) * Dd + c;
                cp16(soff(buf ^ 1, 0) + so, Kh + gi);
                cp16(soff(buf ^ 1, 1) + so, Kl + gi);
                cp16(soff(buf ^ 1, 2) + so, Vh + gi);
                cp16(soff(buf ^ 1, 3) + so, Vl + gi);
            }
            CP_COMMIT();
            CP_WAIT1();
        } else {
            CP_WAIT0();
        }
        __syncthreads();

        float S[8][4];
#pragma unroll
        for (int i = 0; i < 8; i++)
#pragma unroll
            for (int e = 0; e < 4; e++) S[i][e] = 0.f;

#pragma unroll
        for (int jg = 0; jg < 4; jg++) {
#pragma unroll
            for (int kk = 0; kk < 4; kk++) {
                uint32_t ao = (uint32_t)((jg * 16 + klrow) * SROW + kk * 16 + klk) * 2;
                uint32_t kh0, kh1, kh2, kh3, kl0, kl1, kl2, kl3;
                ldmx4(kh0, kh1, kh2, kh3, soff(buf, 0) + ao);
                ldmx4(kl0, kl1, kl2, kl3, soff(buf, 1) + ao);
                mma16816(S[jg * 2 + 0], QHf[kk], kh0, kh2);
                mma16816(S[jg * 2 + 0], QLf[kk], kh0, kh2);
                mma16816(S[jg * 2 + 0], QHf[kk], kl0, kl2);
                mma16816(S[jg * 2 + 1], QHf[kk], kh1, kh3);
                mma16816(S[jg * 2 + 1], QLf[kk], kh1, kh3);
                mma16816(S[jg * 2 + 1], QHf[kk], kl1, kl3);
            }
        }

        if (jt == qt) {
            const int r0l = wid * 16 + (lane >> 2);
            const int cb  = (lane & 3) * 2;
#pragma unroll
            for (int nf = 0; nf < 8; nf++) {
                int c0 = nf * 8 + cb;
                if (c0     > r0l)     S[nf][0] = -1e30f;
                if (c0 + 1 > r0l)     S[nf][1] = -1e30f;
                if (c0     > r0l + 8) S[nf][2] = -1e30f;
                if (c0 + 1 > r0l + 8) S[nf][3] = -1e30f;
            }
        }

        float tm0 = -1e30f, tm1 = -1e30f;
#pragma unroll
        for (int nf = 0; nf < 8; nf++) {
            tm0 = fmaxf(tm0, fmaxf(S[nf][0], S[nf][1]));
            tm1 = fmaxf(tm1, fmaxf(S[nf][2], S[nf][3]));
        }
        tm0 = fmaxf(tm0, __shfl_xor_sync(0xffffffff, tm0, 1));
        tm0 = fmaxf(tm0, __shfl_xor_sync(0xffffffff, tm0, 2));
        tm1 = fmaxf(tm1, __shfl_xor_sync(0xffffffff, tm1, 1));
        tm1 = fmaxf(tm1, __shfl_xor_sync(0xffffffff, tm1, 2));

        float m0n = fmaxf(m0, tm0), m1n = fmaxf(m1, tm1);
        float sc0 = __expf(m0 - m0n), sc1 = __expf(m1 - m1n);
        l0 *= sc0; l1 *= sc1;
#pragma unroll
        for (int i = 0; i < 8; i++) {
            O[i][0] *= sc0; O[i][1] *= sc0;
            O[i][2] *= sc1; O[i][3] *= sc1;
        }
#pragma unroll
        for (int nf = 0; nf < 8; nf++) {
            S[nf][0] = __expf(S[nf][0] - m0n);
            S[nf][1] = __expf(S[nf][1] - m0n);
            S[nf][2] = __expf(S[nf][2] - m1n);
            S[nf][3] = __expf(S[nf][3] - m1n);
            l0 += S[nf][0] + S[nf][1];
            l1 += S[nf][2] + S[nf][3];
        }
        m0 = m0n; m1 = m1n;

#pragma unroll
        for (int kk = 0; kk < 4; kk++) {
            const float* s0 = S[2 * kk];
            const float* s1 = S[2 * kk + 1];
            uint32_t PH[4], PL[4];
            PH[0] = packbf(s0[0], s0[1]);
            PH[1] = packbf(s0[2], s0[3]);
            PH[2] = packbf(s1[0], s1[1]);
            PH[3] = packbf(s1[2], s1[3]);
#pragma unroll
            for (int e = 0; e < 4; e++) {
                const float* sv = (e < 2) ? s0 : s1;
                float c0 = sv[(e & 1) * 2], c1 = sv[(e & 1) * 2 + 1];
                float f0 = __uint_as_float(PH[e] << 16);
                float f1 = __uint_as_float(PH[e] & 0xffff0000u);
                PL[e] = packbf(c0 - f0, c1 - f1);
            }
#pragma unroll
            for (int dc = 0; dc < 4; dc++) {
                uint32_t vo = (uint32_t)((kk * 16 + vrow_in) * SROW + dc * 16 + vcol_of) * 2;
                uint32_t vh0, vh1, vh2, vh3, vl0, vl1, vl2, vl3;
                ldmx4t(vh0, vh1, vh2, vh3, soff(buf, 2) + vo);
                ldmx4t(vl0, vl1, vl2, vl3, soff(buf, 3) + vo);
                mma16816(O[dc * 2 + 0], PH, vh0, vh1);
                mma16816(O[dc * 2 + 0], PL, vh0, vh1);
                mma16816(O[dc * 2 + 0], PH, vl0, vl1);
                mma16816(O[dc * 2 + 1], PH, vh2, vh3);
                mma16816(O[dc * 2 + 1], PL, vh2, vh3);
                mma16816(O[dc * 2 + 1], PH, vl2, vl3);
            }
        }
    }

    l0 += __shfl_xor_sync(0xffffffff, l0, 1);
    l0 += __shfl_xor_sync(0xffffffff, l0, 2);
    l1 += __shfl_xor_sync(0xffffffff, l1, 1);
    l1 += __shfl_xor_sync(0xffffffff, l1, 2);
    const float i0 = 1.f / l0, i1 = 1.f / l1;

    // Epilogue: bf16 hi -> g_ah ; fp8 hi/lo -> g_a8h / g_a8l
    const int b = bh >> 4, h = bh & 15;
    const int t0 = q0 + wid * 16 + (lane >> 2);
    const int t1 = t0 + 8;
    const size_t co = (size_t)h * Dd + (lane & 3) * 2;
    const size_t ro0 = (size_t)(b * Tt + t0) * Cc + co;
    const size_t ro1 = (size_t)(b * Tt + t1) * Cc + co;
#pragma unroll
    for (int nf = 0; nf < 8; nf++) {
        float v0 = O[nf][0] * i0, v1 = O[nf][1] * i0;
        float v2 = O[nf][2] * i1, v3 = O[nf][3] * i1;
        __nv_bfloat16 h0 = __float2bfloat16(v0), h1 = __float2bfloat16(v1);
        __nv_bfloat16 h2 = __float2bfloat16(v2), h3 = __float2bfloat16(v3);
        __nv_bfloat162 w;
        w.x = h0; w.y = h1; *(__nv_bfloat162*)(g_ah + ro0 + nf * 8) = w;
        w.x = h2; w.y = h3; *(__nv_bfloat162*)(g_ah + ro1 + nf * 8) = w;
        *(uint16_t*)(g_a8h + ro0 + nf * 8) = pack_e4m3(v0 * SH_A, v1 * SH_A);
        *(uint16_t*)(g_a8h + ro1 + nf * 8) = pack_e4m3(v2 * SH_A, v3 * SH_A);
        *(uint16_t*)(g_a8l + ro0 + nf * 8) =
            pack_e4m3((v0 - __bfloat162float(h0)) * SL_A,
                      (v1 - __bfloat162float(h1)) * SL_A);
        *(uint16_t*)(g_a8l + ro1 + nf * 8) =
            pack_e4m3((v2 - __bfloat162float(h2)) * SL_A,
                      (v3 - __bfloat162float(h3)) * SL_A);
    }
}

// ---------------------------------------------------------------------------
extern "C" void kernel_launch(void* const* d_in, const int* in_sizes, int n_in,
                              void* d_out, int out_size)
{
    const float* x      = (const float*)d_in[0];
    const float* w_attn = (const float*)d_in[1];
    const float* b_attn = (const float*)d_in[2];
    const float* w_proj = (const float*)d_in[3];
    const float* b_proj = (const float*)d_in[4];
    const float* cosp   = (const float*)d_in[5];
    const float* sinp   = (const float*)d_in[6];
    float* out = (float*)d_out;

    void *p_xh, *p_x8h, *p_x8l, *p_wh, *p_w8h, *p_w8l;
    void *p_ph, *p_p8h, *p_p8l, *p_ah, *p_a8h, *p_a8l, *p_qkv;
    cudaGetSymbolAddress(&p_xh, g_xh);
    cudaGetSymbolAddress(&p_x8h, g_x8h);
    cudaGetSymbolAddress(&p_x8l, g_x8l);
    cudaGetSymbolAddress(&p_wh, g_wh);
    cudaGetSymbolAddress(&p_w8h, g_w8h);
    cudaGetSymbolAddress(&p_w8l, g_w8l);
    cudaGetSymbolAddress(&p_ph, g_ph);
    cudaGetSymbolAddress(&p_p8h, g_p8h);
    cudaGetSymbolAddress(&p_p8l, g_p8l);
    cudaGetSymbolAddress(&p_ah, g_ah);
    cudaGetSymbolAddress(&p_a8h, g_a8h);
    cudaGetSymbolAddress(&p_a8l, g_a8l);
    cudaGetSymbolAddress(&p_qkv, g_qkv);

    static bool once = false;
    if (!once) {
        cudaFuncSetAttribute(flash_mma,
                             cudaFuncAttributeMaxDynamicSharedMemorySize, 8 * TILE_B);
        cudaFuncSetAttribute(gemm_hybrid,
                             cudaFuncAttributeMaxDynamicSharedMemorySize, GEMM_SMEM);
        cudaFuncSetAttribute(gemm_hybrid,
                             cudaFuncAttributePreferredSharedMemoryCarveout, 100);
        once = true;
    }

    // 1) splits: x (A-type scales), w_attn / w_proj (B-type scales)
    {
        int n4 = (Mtot * Cc) / 4;
        split_fp8<<<(n4 + 255) / 256, 256>>>(
            (const float4*)x, (__nv_bfloat162*)p_xh,
            (uint16_t*)p_x8h, (uint16_t*)p_x8l, n4, SH_A, SL_A);
    }
    {
        int n4 = (3 * Cc * Cc) / 4;
        split_fp8<<<(n4 + 255) / 256, 256>>>(
            (const float4*)w_attn, (__nv_bfloat162*)p_wh,
            (uint16_t*)p_w8h, (uint16_t*)p_w8l, n4, SH_B, SL_B);
    }
    {
        int n4 = (Cc * Cc) / 4;
        split_fp8<<<(n4 + 255) / 256, 256>>>(
            (const float4*)w_proj, (__nv_bfloat162*)p_ph,
            (uint16_t*)p_p8h, (uint16_t*)p_p8l, n4, SH_B, SL_B);
    }

    // 2) QKV projection (hybrid bf16+fp8 GEMM) -> g_qkv fp32
    {
        dim3 grid((3 * Cc) / 128, Mtot / 128);
        gemm_hybrid<<<grid, 256, GEMM_SMEM>>>(
            (const __nv_bfloat16*)p_xh, (const uint8_t*)p_x8h, (const uint8_t*)p_x8l,
            (const __nv_bfloat16*)p_wh, (const uint8_t*)p_w8h, (const uint8_t*)p_w8l,
            b_attn, (float*)p_qkv, 3 * Cc, Cc);
    }

    // 3) fused RoPE + relayout + bf16 split of q,k,v
    {
        int total = Bb * Tt * NHh * 8;
        rope_split<<<total / 256, 256>>>(cosp, sinp);
    }

    // 4) flash attention -> g_ah (bf16) + g_a8h/g_a8l (fp8)
    {
        dim3 grid(Tt / 64, Bb * NHh);
        flash_mma<<<grid, 128, 8 * TILE_B>>>();
    }

    // 5) output projection (hybrid GEMM)
    {
        dim3 grid(Cc / 128, Mtot / 128);
        gemm_hybrid<<<grid, 256, GEMM_SMEM>>>(
            (const __nv_bfloat16*)p_ah, (const uint8_t*)p_a8h, (const uint8_t*)p_a8l,
            (const __nv_bfloat16*)p_ph, (const uint8_t*)p_p8h, (const uint8_t*)p_p8l,
            b_proj, out, Cc, Cc);
    }
}

// round 10
// speedup vs baseline: 2.7190x; 2.7190x over previous
#include <cuda_runtime.h>
#include <cuda_fp16.h>
#include <cstdint>

#define Bb 4
#define Tt 2048
#define Cc 1024
#define NHh 16
#define Dd 64
#define Mtot (Bb * Tt)   // 8192

// ------------------------- scratch (__device__ globals) --------------------
__device__ float g_qkv[(size_t)Bb * Tt * 3 * Cc];    // [B,T,3C] fp32
__device__ __half g_xh[(size_t)Mtot * Cc];
__device__ __half g_wh[(size_t)3 * Cc * Cc];
__device__ __half g_ph[(size_t)Cc * Cc];
__device__ __half g_ah[(size_t)Mtot * Cc];
// head-major [b*16+h][t][d] fp16 for attention
__device__ __half g_qh[(size_t)Mtot * Cc];
__device__ __half g_kh[(size_t)Mtot * Cc];
__device__ __half g_vh[(size_t)Mtot * Cc];

// ------------------------- helpers -----------------------------------------
__device__ __forceinline__ uint32_t smem_u32(const void* p) {
    uint32_t a;
    asm("{ .reg .u64 t; cvta.to.shared.u64 t, %1; cvt.u32.u64 %0, t; }"
        : "=r"(a) : "l"(p));
    return a;
}

__device__ __forceinline__ void ldmx4(uint32_t& r0, uint32_t& r1,
                                      uint32_t& r2, uint32_t& r3, uint32_t addr) {
    asm volatile("ldmatrix.sync.aligned.m8n8.x4.shared.b16 {%0,%1,%2,%3}, [%4];"
                 : "=r"(r0), "=r"(r1), "=r"(r2), "=r"(r3) : "r"(addr));
}

__device__ __forceinline__ void ldmx4t(uint32_t& r0, uint32_t& r1,
                                       uint32_t& r2, uint32_t& r3, uint32_t addr) {
    asm volatile("ldmatrix.sync.aligned.m8n8.x4.trans.shared.b16 {%0,%1,%2,%3}, [%4];"
                 : "=r"(r0), "=r"(r1), "=r"(r2), "=r"(r3) : "r"(addr));
}

__device__ __forceinline__ void mmaf16(float* d, const uint32_t* a,
                                       uint32_t b0, uint32_t b1) {
    asm volatile(
        "mma.sync.aligned.m16n8k16.row.col.f32.f16.f16.f32 "
        "{%0,%1,%2,%3}, {%4,%5,%6,%7}, {%8,%9}, {%0,%1,%2,%3};"
        : "+f"(d[0]), "+f"(d[1]), "+f"(d[2]), "+f"(d[3])
        : "r"(a[0]), "r"(a[1]), "r"(a[2]), "r"(a[3]), "r"(b0), "r"(b1));
}

// pack two fp32 -> f16x2 (low half = first arg)
__device__ __forceinline__ uint32_t packf16(float lo, float hi) {
    uint32_t r;
    asm("cvt.rn.f16x2.f32 %0, %1, %2;" : "=r"(r) : "f"(hi), "f"(lo));
    return r;
}

__device__ __forceinline__ void cp16(uint32_t dst, const void* src) {
    asm volatile("cp.async.cg.shared.global [%0], [%1], 16;" :: "r"(dst), "l"(src));
}
#define CP_COMMIT() asm volatile("cp.async.commit_group;" ::: "memory")
#define CP_WAIT0()  asm volatile("cp.async.wait_group 0;" ::: "memory")
#define CP_WAIT1()  asm volatile("cp.async.wait_group 1;" ::: "memory")

// ---------------------------------------------------------------------------
// fp16 single-pass GEMM via mma.sync, cp.async 2-stage, 2 CTAs/SM.
// C[M,N] = A[M,K] @ B[N,K]^T + bias[N]
// CTA tile 128x128, BK=32, 8 warps (2m x 4n), warp tile 64x32.
// smem: 2 stages x 2 matrices x 128 rows x 80 B = 40960 B.
// ---------------------------------------------------------------------------
#define SPAD 40
#define GMAT (128 * SPAD * 2u)   // 10240 B per matrix per stage

__global__ __launch_bounds__(256, 2)
void gemm_f16(const __half* __restrict__ A,
              const __half* __restrict__ B,
              const float* __restrict__ bias,
              float* __restrict__ Cout, int N, int K)
{
    extern __shared__ char gsm[];
    const uint32_t sb = smem_u32(gsm);

    const int tid  = threadIdx.x;
    const int wid  = tid >> 5;
    const int lane = tid & 31;
    const int mw   = wid >> 2;      // 0..1
    const int nw   = wid & 3;       // 0..3
    const int m0   = blockIdx.y * 128;
    const int n0   = blockIdx.x * 128;

    auto stoff = [&](int s, int m) -> uint32_t {
        return sb + (uint32_t)(s * 2 + m) * GMAT;
    };

    const int r0i = tid >> 2, ci = tid & 3;
    const int r1i = r0i + 64;
    const uint32_t so0 = (uint32_t)(r0i * (SPAD * 2) + ci * 16);
    const uint32_t so1 = (uint32_t)(r1i * (SPAD * 2) + ci * 16);
    const int kq = K >> 3;
    const int nk = K >> 5;

    auto load_stage = [&](int s, int kc) {
        const size_t a0 = (size_t)(m0 + r0i) * kq + kc * 4 + ci;
        const size_t a1 = (size_t)(m0 + r1i) * kq + kc * 4 + ci;
        const size_t b0 = (size_t)(n0 + r0i) * kq + kc * 4 + ci;
        const size_t b1 = (size_t)(n0 + r1i) * kq + kc * 4 + ci;
        cp16(stoff(s, 0) + so0, (const uint4*)A + a0);
        cp16(stoff(s, 0) + so1, (const uint4*)A + a1);
        cp16(stoff(s, 1) + so0, (const uint4*)B + b0);
        cp16(stoff(s, 1) + so1, (const uint4*)B + b1);
    };

    const int lrow = lane & 15;
    const int lk   = (lane >> 4) * 8;
    uint32_t aoff[4], boff[2];
#pragma unroll
    for (int mt = 0; mt < 4; mt++)
        aoff[mt] = (uint32_t)(((mw * 64 + mt * 16 + lrow) * SPAD + lk) * 2);
#pragma unroll
    for (int ng = 0; ng < 2; ng++)
        boff[ng] = (uint32_t)(((nw * 32 + ng * 16 + lrow) * SPAD + lk) * 2);

    float acc[4][4][4];
#pragma unroll
    for (int i = 0; i < 4; i++)
#pragma unroll
        for (int j = 0; j < 4; j++)
#pragma unroll
            for (int e = 0; e < 4; e++) acc[i][j][e] = 0.f;

    load_stage(0, 0);
    CP_COMMIT();

    for (int kc = 0; kc < nk; kc++) {
        const int s = kc & 1;
        if (kc + 1 < nk) {
            load_stage(s ^ 1, kc + 1);
            CP_COMMIT();
            CP_WAIT1();
        } else {
            CP_WAIT0();
        }
        __syncthreads();

        const uint32_t uA = stoff(s, 0), uB = stoff(s, 1);
#pragma unroll
        for (int ks = 0; ks < 2; ks++) {
            const uint32_t kb = ks * 32;
            uint32_t ah[4][4];
#pragma unroll
            for (int mt = 0; mt < 4; mt++)
                ldmx4(ah[mt][0], ah[mt][1], ah[mt][2], ah[mt][3], uA + aoff[mt] + kb);
            uint32_t bh[2][4];
#pragma unroll
            for (int ng = 0; ng < 2; ng++)
                ldmx4(bh[ng][0], bh[ng][1], bh[ng][2], bh[ng][3], uB + boff[ng] + kb);
#pragma unroll
            for (int mt = 0; mt < 4; mt++)
#pragma unroll
                for (int ng = 0; ng < 2; ng++)
#pragma unroll
                    for (int sub = 0; sub < 2; sub++)
                        mmaf16(acc[mt][ng * 2 + sub], ah[mt],
                               bh[ng][sub], bh[ng][sub + 2]);
        }
        __syncthreads();
    }

    const int erow = lane >> 2;
    const int ecol = (lane & 3) * 2;
#pragma unroll
    for (int mt = 0; mt < 4; mt++) {
#pragma unroll
        for (int nt = 0; nt < 4; nt++) {
            const int row = m0 + mw * 64 + mt * 16 + erow;
            const int col = n0 + nw * 32 + nt * 8 + ecol;
            const float b0 = bias[col], b1 = bias[col + 1];
            float2 v;
            v.x = acc[mt][nt][0] + b0;
            v.y = acc[mt][nt][1] + b1;
            *(float2*)(Cout + (size_t)row * N + col) = v;
            v.x = acc[mt][nt][2] + b0;
            v.y = acc[mt][nt][3] + b1;
            *(float2*)(Cout + (size_t)(row + 8) * N + col) = v;
        }
    }
}
#define GEMM_SMEM (2u * 2u * GMAT)   // 40960

// ---------------------------------------------------------------------------
// fp32 -> fp16, vectorized by 4
// ---------------------------------------------------------------------------
__global__ void cvt_f32_f16(const float4* __restrict__ src,
                            __half2* __restrict__ dst, int n4)
{
    int i = blockIdx.x * 256 + threadIdx.x;
    if (i >= n4) return;
    float4 v = src[i];
    dst[2 * i]     = __floats2half2_rn(v.x, v.y);
    dst[2 * i + 1] = __floats2half2_rn(v.z, v.w);
}

// ---------------------------------------------------------------------------
// Fused RoPE + head-major relayout + fp16 convert of q,k,v.
// q pre-scaled by 1/sqrt(D).
// ---------------------------------------------------------------------------
__global__ void rope_f16(const float* __restrict__ cosp,
                         const float* __restrict__ sinp)
{
    int idx = blockIdx.x * 256 + threadIdx.x;
    int ds = idx & 7;
    int h  = (idx >> 3) & 15;
    int t  = (idx >> 7) & 2047;
    int b  = idx >> 18;
    int d0 = ds * 4;

    const float* base = g_qkv + ((size_t)(b * Tt + t)) * (3 * Cc) + h * Dd;
    float4 q1 = *(const float4*)(base + d0);
    float4 q2 = *(const float4*)(base + d0 + 32);
    float4 k1 = *(const float4*)(base + Cc + d0);
    float4 k2 = *(const float4*)(base + Cc + d0 + 32);
    float4 v1 = *(const float4*)(base + 2 * Cc + d0);
    float4 v2 = *(const float4*)(base + 2 * Cc + d0 + 32);
    float4 cw = *(const float4*)(cosp + t * Dd + d0);
    float4 sw = *(const float4*)(sinp + t * Dd + d0);

    const float sc = 0.125f;
    size_t ob = (((size_t)(b * NHh + h)) * Tt + t) * Dd;
    __half2* qp = (__half2*)(g_qh + ob + d0);
    __half2* kp = (__half2*)(g_kh + ob + d0);
    __half2* vp = (__half2*)(g_vh + ob + d0);

    qp[0] = __floats2half2_rn((q1.x * cw.x - q2.x * sw.x) * sc,
                              (q1.y * cw.y - q2.y * sw.y) * sc);
    qp[1] = __floats2half2_rn((q1.z * cw.z - q2.z * sw.z) * sc,
                              (q1.w * cw.w - q2.w * sw.w) * sc);
    qp[16] = __floats2half2_rn((q2.x * cw.x + q1.x * sw.x) * sc,
                               (q2.y * cw.y + q1.y * sw.y) * sc);
    qp[17] = __floats2half2_rn((q2.z * cw.z + q1.z * sw.z) * sc,
                               (q2.w * cw.w + q1.w * sw.w) * sc);

    kp[0] = __floats2half2_rn(k1.x * cw.x - k2.x * sw.x,
                              k1.y * cw.y - k2.y * sw.y);
    kp[1] = __floats2half2_rn(k1.z * cw.z - k2.z * sw.z,
                              k1.w * cw.w - k2.w * sw.w);
    kp[16] = __floats2half2_rn(k2.x * cw.x + k1.x * sw.x,
                               k2.y * cw.y + k1.y * sw.y);
    kp[17] = __floats2half2_rn(k2.z * cw.z + k1.z * sw.z,
                               k2.w * cw.w + k1.w * sw.w);

    vp[0]  = __floats2half2_rn(v1.x, v1.y);
    vp[1]  = __floats2half2_rn(v1.z, v1.w);
    vp[16] = __floats2half2_rn(v2.x, v2.y);
    vp[17] = __floats2half2_rn(v2.z, v2.w);
}

// ---------------------------------------------------------------------------
// Flash attention on fp16 mma.sync (fp32 softmax).
// Grid (32, 64): CTA = 64 q rows of one (b,h); 4 warps x 16 rows.
// K/V tiles (64 keys) double-buffered via cp.async. Epilogue -> g_ah fp16.
// smem: 2 bufs x {K,V} + Q = 5 x 9216 = 46080 B.
// ---------------------------------------------------------------------------
#define SROW 72
#define TILE_B 9216u
#define FLASH_SMEM (5u * TILE_B)

__global__ __launch_bounds__(128, 2) void flash_mma()
{
    extern __shared__ char fsm[];
    const uint32_t sb = smem_u32(fsm);

    const int bh = blockIdx.y;
    const int qt = (gridDim.x - 1) - blockIdx.x;
    const int q0 = qt * 64;
    const int tid = threadIdx.x, wid = tid >> 5, lane = tid & 31;

    const size_t hb = (size_t)bh * Tt * Dd;
    const __half* Q = g_qh + hb + (size_t)q0 * Dd;
    const __half* Kp = g_kh + hb;
    const __half* Vp = g_vh + hb;

    auto soff = [&](int buf, int mat) -> uint32_t {
        return sb + (uint32_t)(buf * 2 + mat) * TILE_B;
    };
    const uint32_t soffQ = sb + 4 * TILE_B;

    // prologue: Q + tile 0
    {
#pragma unroll
        for (int i = 0; i < 4; i++) {
            int lin = tid + i * 128;
            int r = lin >> 3, c = (lin & 7) * 8;
            uint32_t so = (uint32_t)(r * SROW + c) * 2;
            cp16(soffQ + so, Q + (size_t)r * Dd + c);
        }
        CP_COMMIT();
#pragma unroll
        for (int i = 0; i < 4; i++) {
            int lin = tid + i * 128;
            int r = lin >> 3, c = (lin & 7) * 8;
            uint32_t so = (uint32_t)(r * SROW + c) * 2;
            cp16(soff(0, 0) + so, Kp + (size_t)r * Dd + c);
            cp16(soff(0, 1) + so, Vp + (size_t)r * Dd + c);
        }
        CP_COMMIT();
        CP_WAIT0();
        __syncthreads();
    }

    uint32_t QF[4][4];
    {
        const int row = wid * 16 + (lane & 15);
        const int ck  = (lane >> 4) * 8;
#pragma unroll
        for (int kk = 0; kk < 4; kk++) {
            uint32_t ao = (uint32_t)(row * SROW + kk * 16 + ck) * 2;
            ldmx4(QF[kk][0], QF[kk][1], QF[kk][2], QF[kk][3], soffQ + ao);
        }
    }

    float O[8][4];
#pragma unroll
    for (int i = 0; i < 8; i++)
#pragma unroll
        for (int e = 0; e < 4; e++) O[i][e] = 0.f;
    float m0 = -1e30f, m1 = -1e30f, l0 = 0.f, l1 = 0.f;

    const int klrow = lane & 15;
    const int klk   = (lane >> 4) * 8;
    const int vg    = lane >> 3;
    const int vrow_in = (vg & 1) * 8 + (lane & 7);
    const int vcol_of = (vg >> 1) * 8;

    for (int jt = 0; jt <= qt; jt++) {
        const int buf = jt & 1;
        __syncthreads();
        if (jt < qt) {
            const int j1 = (jt + 1) * 64;
#pragma unroll
            for (int i = 0; i < 4; i++) {
                int lin = tid + i * 128;
                int r = lin >> 3, c = (lin & 7) * 8;
                uint32_t so = (uint32_t)(r * SROW + c) * 2;
                size_t gi = (size_t)(j1 + r) * Dd + c;
                cp16(soff(buf ^ 1, 0) + so, Kp + gi);
                cp16(soff(buf ^ 1, 1) + so, Vp + gi);
            }
            CP_COMMIT();
            CP_WAIT1();
        } else {
            CP_WAIT0();
        }
        __syncthreads();

        float S[8][4];
#pragma unroll
        for (int i = 0; i < 8; i++)
#pragma unroll
            for (int e = 0; e < 4; e++) S[i][e] = 0.f;

#pragma unroll
        for (int jg = 0; jg < 4; jg++) {
#pragma unroll
            for (int kk = 0; kk < 4; kk++) {
                uint32_t ao = (uint32_t)((jg * 16 + klrow) * SROW + kk * 16 + klk) * 2;
                uint32_t k0, k1, k2, k3;
                ldmx4(k0, k1, k2, k3, soff(buf, 0) + ao);
                mmaf16(S[jg * 2 + 0], QF[kk], k0, k2);
                mmaf16(S[jg * 2 + 1], QF[kk], k1, k3);
            }
        }

        if (jt == qt) {
            const int r0l = wid * 16 + (lane >> 2);
            const int cb  = (lane & 3) * 2;
#pragma unroll
            for (int nf = 0; nf < 8; nf++) {
                int c0 = nf * 8 + cb;
                if (c0     > r0l)     S[nf][0] = -1e30f;
                if (c0 + 1 > r0l)     S[nf][1] = -1e30f;
                if (c0     > r0l + 8) S[nf][2] = -1e30f;
                if (c0 + 1 > r0l + 8) S[nf][3] = -1e30f;
            }
        }

        float tm0 = -1e30f, tm1 = -1e30f;
#pragma unroll
        for (int nf = 0; nf < 8; nf++) {
            tm0 = fmaxf(tm0, fmaxf(S[nf][0], S[nf][1]));
            tm1 = fmaxf(tm1, fmaxf(S[nf][2], S[nf][3]));
        }
        tm0 = fmaxf(tm0, __shfl_xor_sync(0xffffffff, tm0, 1));
        tm0 = fmaxf(tm0, __shfl_xor_sync(0xffffffff, tm0, 2));
        tm1 = fmaxf(tm1, __shfl_xor_sync(0xffffffff, tm1, 1));
        tm1 = fmaxf(tm1, __shfl_xor_sync(0xffffffff, tm1, 2));

        float m0n = fmaxf(m0, tm0), m1n = fmaxf(m1, tm1);
        float sc0 = __expf(m0 - m0n), sc1 = __expf(m1 - m1n);
        l0 *= sc0; l1 *= sc1;
#pragma unroll
        for (int i = 0; i < 8; i++) {
            O[i][0] *= sc0; O[i][1] *= sc0;
            O[i][2] *= sc1; O[i][3] *= sc1;
        }
#pragma unroll
        for (int nf = 0; nf < 8; nf++) {
            S[nf][0] = __expf(S[nf][0] - m0n);
            S[nf][1] = __expf(S[nf][1] - m0n);
            S[nf][2] = __expf(S[nf][2] - m1n);
            S[nf][3] = __expf(S[nf][3] - m1n);
            l0 += S[nf][0] + S[nf][1];
            l1 += S[nf][2] + S[nf][3];
        }
        m0 = m0n; m1 = m1n;

#pragma unroll
        for (int kk = 0; kk < 4; kk++) {
            const float* s0 = S[2 * kk];
            const float* s1 = S[2 * kk + 1];
            uint32_t P[4];
            P[0] = packf16(s0[0], s0[1]);
            P[1] = packf16(s0[2], s0[3]);
            P[2] = packf16(s1[0], s1[1]);
            P[3] = packf16(s1[2], s1[3]);
#pragma unroll
            for (int dc = 0; dc < 4; dc++) {
                uint32_t vo = (uint32_t)((kk * 16 + vrow_in) * SROW + dc * 16 + vcol_of) * 2;
                uint32_t v0, v1, v2, v3;
                ldmx4t(v0, v1, v2, v3, soff(buf, 1) + vo);
                mmaf16(O[dc * 2 + 0], P, v0, v1);
                mmaf16(O[dc * 2 + 1], P, v2, v3);
            }
        }
    }

    l0 += __shfl_xor_sync(0xffffffff, l0, 1);
    l0 += __shfl_xor_sync(0xffffffff, l0, 2);
    l1 += __shfl_xor_sync(0xffffffff, l1, 1);
    l1 += __shfl_xor_sync(0xffffffff, l1, 2);
    const float i0 = 1.f / l0, i1 = 1.f / l1;

    // Epilogue: fp16 -> g_ah (proj GEMM A input)
    const int b = bh >> 4, h = bh & 15;
    const int t0 = q0 + wid * 16 + (lane >> 2);
    const int t1 = t0 + 8;
    const size_t co = (size_t)h * Dd + (lane & 3) * 2;
    __half2* a0 = (__half2*)(g_ah + (size_t)(b * Tt + t0) * Cc + co);
    __half2* a1 = (__half2*)(g_ah + (size_t)(b * Tt + t1) * Cc + co);
#pragma unroll
    for (int nf = 0; nf < 8; nf++) {
        a0[nf * 4] = __floats2half2_rn(O[nf][0] * i0, O[nf][1] * i0);
        a1[nf * 4] = __floats2half2_rn(O[nf][2] * i1, O[nf][3] * i1);
    }
}

// ---------------------------------------------------------------------------
extern "C" void kernel_launch(void* const* d_in, const int* in_sizes, int n_in,
                              void* d_out, int out_size)
{
    const float* x      = (const float*)d_in[0];
    const float* w_attn = (const float*)d_in[1];
    const float* b_attn = (const float*)d_in[2];
    const float* w_proj = (const float*)d_in[3];
    const float* b_proj = (const float*)d_in[4];
    const float* cosp   = (const float*)d_in[5];
    const float* sinp   = (const float*)d_in[6];
    float* out = (float*)d_out;

    void *p_xh, *p_wh, *p_ph, *p_ah, *p_qkv;
    cudaGetSymbolAddress(&p_xh, g_xh);
    cudaGetSymbolAddress(&p_wh, g_wh);
    cudaGetSymbolAddress(&p_ph, g_ph);
    cudaGetSymbolAddress(&p_ah, g_ah);
    cudaGetSymbolAddress(&p_qkv, g_qkv);

    static bool once = false;
    if (!once) {
        cudaFuncSetAttribute(flash_mma,
                             cudaFuncAttributeMaxDynamicSharedMemorySize, FLASH_SMEM);
        cudaFuncSetAttribute(gemm_f16,
                             cudaFuncAttributeMaxDynamicSharedMemorySize, GEMM_SMEM);
        cudaFuncSetAttribute(gemm_f16,
                             cudaFuncAttributePreferredSharedMemoryCarveout, 100);
        once = true;
    }

    // 1) fp16 conversions of x, w_attn, w_proj
    {
        int n4 = (Mtot * Cc) / 4;
        cvt_f32_f16<<<(n4 + 255) / 256, 256>>>(
            (const float4*)x, (__half2*)p_xh, n4);
    }
    {
        int n4 = (3 * Cc * Cc) / 4;
        cvt_f32_f16<<<(n4 + 255) / 256, 256>>>(
            (const float4*)w_attn, (__half2*)p_wh, n4);
    }
    {
        int n4 = (Cc * Cc) / 4;
        cvt_f32_f16<<<(n4 + 255) / 256, 256>>>(
            (const float4*)w_proj, (__half2*)p_ph, n4);
    }

    // 2) QKV projection (fp16 single-pass GEMM) -> g_qkv fp32
    {
        dim3 grid((3 * Cc) / 128, Mtot / 128);
        gemm_f16<<<grid, 256, GEMM_SMEM>>>(
            (const __half*)p_xh, (const __half*)p_wh,
            b_attn, (float*)p_qkv, 3 * Cc, Cc);
    }

    // 3) fused RoPE + relayout + fp16 convert of q,k,v
    {
        int total = Bb * Tt * NHh * 8;
        rope_f16<<<total / 256, 256>>>(cosp, sinp);
    }

    // 4) flash attention (fp16) -> g_ah fp16
    {
        dim3 grid(Tt / 64, Bb * NHh);
        flash_mma<<<grid, 128, FLASH_SMEM>>>();
    }

    // 5) output projection (fp16 single-pass GEMM)
    {
        dim3 grid(Cc / 128, Mtot / 128);
        gemm_f16<<<grid, 256, GEMM_SMEM>>>(
            (const __half*)p_ah, (const __half*)p_ph,
            b_proj, out, Cc, Cc);
    }
}